// round 14
// baseline (speedup 1.0000x reference)
#include <cuda_runtime.h>
#include <cuda_bf16.h>
#include <cstdint>

// Per-row histogram: x[4096,16384] fp32 -> out[4096,30] fp32 (permuted order).
//
// R9 vs R8: half-row CTAs where the 4-stage ring holds the ENTIRE work unit
// (4 x 8KB issued in the prologue; no refills, no empty barriers, no producer
// loop). mbarrier wait is lane0-only + __syncwarp (R8 issued a ~90cyc TRYWAIT
// in all 32 lanes, 8x per row -> issue was 55% with only ~7 instr/elem of
// real work). Two CTAs per row combine via atomicAdd on out (exact integer
// floats -> deterministic); a tiny pre-kernel zeroes out first.
//
// Consumer: 4x LDS.128/thread/chunk -> one-hot (1u<<bin) -> 7 register
// bit-plane CSA counters (weights 1..64, cap 127; 64 elem/thread -> safe).
// Bin math: t = fma(x,7/3,15); t = min(t,29); k = cvt.rmi.u32(t).

#define NT     128
#define COLS   16384
#define NBINS  30
#define STAGES 4
#define CHUNKB 8192                    // bytes per stage
#define HALFB  (COLS * 4 / 2)          // 32768 bytes per CTA (half row)

__device__ __forceinline__ uint32_t smem_u32(const void* p) {
    uint32_t a;
    asm("{ .reg .u64 t; cvta.to.shared.u64 t, %1; cvt.u32.u64 %0, t; }"
        : "=r"(a) : "l"(p));
    return a;
}

__device__ __forceinline__ void csa(unsigned& sum, unsigned& carry,
                                    unsigned a, unsigned b, unsigned c) {
    unsigned u = a ^ b;
    sum   = u ^ c;                 // LOP3 0x96
    carry = (a & b) | (u & c);     // LOP3 0xE8
}

__device__ __forceinline__ unsigned bin_onehot(float v) {
    const float SCALE = 2.3333333333333335f;  // 7/3 = 1/binwidth
    const float OFF   = 15.0f;                // 1 - LO/w
    return 1u << __float2uint_rd(fminf(fmaf(v, SCALE, OFF), 29.0f));
}

__device__ __forceinline__ unsigned warp_bit_transpose(unsigned x, int lane) {
    #pragma unroll
    for (int st = 0; st < 5; st++) {
        const int s = 16 >> st;
        const unsigned m = (st == 0) ? 0x0000FFFFu :
                           (st == 1) ? 0x00FF00FFu :
                           (st == 2) ? 0x0F0F0F0Fu :
                           (st == 3) ? 0x33333333u : 0x55555555u;
        unsigned y = __shfl_xor_sync(0xffffffffu, x, s);
        x = (lane & s) ? ((x & ~m) | ((y & ~m) >> s))
                       : ((x &  m) | ((y &  m) << s));
    }
    return x;
}

__global__ void zero_out(float* out, int n) {
    int i = blockIdx.x * blockDim.x + threadIdx.x;
    if (i < n) out[i] = 0.0f;
}

__global__ __launch_bounds__(NT)
void hist_kernel(const float* __restrict__ x, float* __restrict__ out) {
    __shared__ __align__(1024) float4 buf[STAGES][CHUNKB / 16];
    __shared__ __align__(8) unsigned long long mbar[STAGES];
    __shared__ unsigned swcnt[NT / 32][32];

    const int tid  = threadIdx.x;
    const int lane = tid & 31;
    const int warp = tid >> 5;
    const int row  = blockIdx.x >> 1;
    const int half = blockIdx.x & 1;

    const char* src = reinterpret_cast<const char*>(x)
                    + (size_t)row * (COLS * 4) + half * HALFB;

    // Prologue: init barriers and issue the ENTIRE half-row (4 x 8KB TMA).
    if (tid == 0) {
        #pragma unroll
        for (int s = 0; s < STAGES; s++)
            asm volatile("mbarrier.init.shared.b64 [%0], 1;"
                         :: "r"(smem_u32(&mbar[s])) : "memory");
        asm volatile("fence.proxy.async.shared::cta;" ::: "memory");
        #pragma unroll
        for (int s = 0; s < STAGES; s++) {
            uint32_t mb = smem_u32(&mbar[s]);
            asm volatile("mbarrier.arrive.expect_tx.shared.b64 _, [%0], %1;"
                         :: "r"(mb), "r"(CHUNKB) : "memory");
            asm volatile(
                "cp.async.bulk.shared::cluster.global.mbarrier::complete_tx::bytes"
                " [%0], [%1], %2, [%3];"
                :: "r"(smem_u32(&buf[s][0])), "l"(src + s * CHUNKB),
                   "r"(CHUNKB), "r"(mb) : "memory");
        }
    }
    __syncthreads();   // barriers valid before any consumer waits on them

    // 7 bit-plane counters, weights 1..64 (cap 127; 64 elem/thread -> safe)
    unsigned ones = 0, twos = 0, fours = 0;
    unsigned a8 = 0, a16 = 0, a32 = 0, a64 = 0;

    #pragma unroll
    for (int c = 0; c < STAGES; c++) {
        // Each stage is consumed exactly once: parity always 0.
        // Lane0 polls; the rest sleep at syncwarp (1 TRYWAIT per warp, not 32).
        if (lane == 0) {
            asm volatile(
                "{\n\t.reg .pred P;\n"
                "W%=:\n\t"
                "mbarrier.try_wait.parity.acquire.cta.shared::cta.b64 P, [%0], 0, 0x989680;\n\t"
                "@P bra D%=;\n\t"
                "bra W%=;\n"
                "D%=:\n\t}"
                :: "r"(smem_u32(&mbar[c])) : "memory");
        }
        __syncwarp();

        const float4* b = &buf[c][0];
        float4 va = b[tid];
        float4 vb = b[tid + 128];
        float4 vc = b[tid + 256];
        float4 vd = b[tid + 384];

        unsigned h0 = bin_onehot(va.x), h1 = bin_onehot(va.y);
        unsigned h2 = bin_onehot(va.z), h3 = bin_onehot(va.w);
        unsigned h4 = bin_onehot(vb.x), h5 = bin_onehot(vb.y);
        unsigned h6 = bin_onehot(vb.z), h7 = bin_onehot(vb.w);
        unsigned g0 = bin_onehot(vc.x), g1 = bin_onehot(vc.y);
        unsigned g2 = bin_onehot(vc.z), g3 = bin_onehot(vc.w);
        unsigned g4 = bin_onehot(vd.x), g5 = bin_onehot(vd.y);
        unsigned g6 = bin_onehot(vd.z), g7 = bin_onehot(vd.w);

        unsigned c2a, c2b, c4a, c4b, e8a, e8b;
        csa(ones, c2a, ones, h0, h1);
        csa(ones, c2b, ones, h2, h3);
        csa(twos, c4a, twos, c2a, c2b);
        csa(ones, c2a, ones, h4, h5);
        csa(ones, c2b, ones, h6, h7);
        csa(twos, c4b, twos, c2a, c2b);
        csa(fours, e8a, fours, c4a, c4b);
        csa(ones, c2a, ones, g0, g1);
        csa(ones, c2b, ones, g2, g3);
        csa(twos, c4a, twos, c2a, c2b);
        csa(ones, c2a, ones, g4, g5);
        csa(ones, c2b, ones, g6, g7);
        csa(twos, c4b, twos, c2a, c2b);
        csa(fours, e8b, fours, c4a, c4b);
        unsigned c16;
        csa(a8, c16, a8, e8a, e8b);
        unsigned cc = a16 & c16; a16 ^= c16;
        unsigned dd = a32 & cc;  a32 ^= cc;
        a64 ^= dd;                 // weight-64 plane cannot carry out (cap 127)
    }

    // Transpose planes so lane b holds bin b; weighted popcounts.
    unsigned planes[7] = {ones, twos, fours, a8, a16, a32, a64};
    unsigned cnt = 0;
    #pragma unroll
    for (int j = 0; j < 7; j++) {
        unsigned t = warp_bit_transpose(planes[j], lane);
        cnt += (unsigned)__popc(t) << j;
    }
    swcnt[warp][lane] = cnt;
    __syncthreads();
    if (warp == 0 && lane < NBINS) {
        unsigned total = swcnt[0][lane] + swcnt[1][lane]
                       + swcnt[2][lane] + swcnt[3][lane];
        int pos = (lane == 0) ? 0 : (lane == NBINS - 1) ? 1 : (lane + 1);
        // Two half-row CTAs combine; counts are exact integers in fp32,
        // so the atomic add order cannot change the result.
        atomicAdd(&out[(size_t)row * NBINS + pos], (float)total);
    }
}

extern "C" void kernel_launch(void* const* d_in, const int* in_sizes, int n_in,
                              void* d_out, int out_size) {
    const float* x = (const float*)d_in[0];
    float* out = (float*)d_out;
    int rows = in_sizes[0] / COLS;
    zero_out<<<(rows * NBINS + 255) / 256, 256>>>(out, rows * NBINS);
    hist_kernel<<<rows * 2, NT>>>(x, out);
}

// round 15
// speedup vs baseline: 1.8886x; 1.8886x over previous
#include <cuda_runtime.h>
#include <cuda_bf16.h>
#include <cstdint>

// Per-row histogram: x[4096,16384] fp32 -> out[4096,30] fp32 (permuted order).
//
// R10: PERSISTENT version of the R8 producer/consumer TMA ring (R8 = 45.6us,
// 77% DRAM). R9 proved the ring's value is CONTINUITY: its per-CTA cold-start
// design collapsed to 37% DRAM. Here 888 persistent CTAs (6/SM x 148) each
// stream ALL their rows through one never-draining 4-stage x 8KB ring: the
// producer's global chunk counter rolls across row boundaries, so ring-fill
// latency is paid 888x total (vs 4096 wave-exposed starts in R8, 8192 in R9).
//
// Consumer (unchanged from R8): per-thread mbarrier wait, 4x LDS.128 ->
// one-hot (1u<<bin) -> 8 register bit-plane CSA counters (weights 1..128,
// cap 255; 128 elem/thread/row -> safe). Row flush every 8 chunks: 32x32
// warp bit-transpose, weighted popcounts, 2x syncthreads, direct store
// (CTA owns the row -> no atomics, no output zeroing).
// Bin math: t = fma(x,7/3,15); t = min(t,29); k = cvt.rmi.u32(t).

#define NT     128
#define COLS   16384
#define ROWB   (COLS * 4)            // 65536 bytes per row
#define NBINS  30
#define STAGES 4
#define CHUNKB 8192                  // bytes per stage
#define CPR    (ROWB / CHUNKB)       // 8 chunks per row
#define GRID   888                   // 148 SMs x 6 CTAs (smem-limited)

__device__ __forceinline__ uint32_t smem_u32(const void* p) {
    uint32_t a;
    asm("{ .reg .u64 t; cvta.to.shared.u64 t, %1; cvt.u32.u64 %0, t; }"
        : "=r"(a) : "l"(p));
    return a;
}

__device__ __forceinline__ void csa(unsigned& sum, unsigned& carry,
                                    unsigned a, unsigned b, unsigned c) {
    unsigned u = a ^ b;
    sum   = u ^ c;                 // LOP3 0x96
    carry = (a & b) | (u & c);     // LOP3 0xE8
}

__device__ __forceinline__ unsigned bin_onehot(float v) {
    const float SCALE = 2.3333333333333335f;  // 7/3 = 1/binwidth
    const float OFF   = 15.0f;                // 1 - LO/w
    return 1u << __float2uint_rd(fminf(fmaf(v, SCALE, OFF), 29.0f));
}

__device__ __forceinline__ unsigned warp_bit_transpose(unsigned x, int lane) {
    #pragma unroll
    for (int st = 0; st < 5; st++) {
        const int s = 16 >> st;
        const unsigned m = (st == 0) ? 0x0000FFFFu :
                           (st == 1) ? 0x00FF00FFu :
                           (st == 2) ? 0x0F0F0F0Fu :
                           (st == 3) ? 0x33333333u : 0x55555555u;
        unsigned y = __shfl_xor_sync(0xffffffffu, x, s);
        x = (lane & s) ? ((x & ~m) | ((y & ~m) >> s))
                       : ((x &  m) | ((y &  m) << s));
    }
    return x;
}

// Blocking parity wait on an mbarrier.
#define MB_WAIT(mb, parity)                                                   \
    asm volatile(                                                             \
        "{\n\t.reg .pred P;\n"                                                \
        "W%=:\n\t"                                                            \
        "mbarrier.try_wait.parity.acquire.cta.shared::cta.b64 P, [%0], %1, 0x989680;\n\t" \
        "@P bra D%=;\n\t"                                                     \
        "bra W%=;\n"                                                          \
        "D%=:\n\t}"                                                           \
        :: "r"(mb), "r"(parity) : "memory")

// TMA refill of stage s from byte offset `off` in x.
#define REFILL(sm_stage, mb, srcp)                                            \
    do {                                                                      \
        asm volatile("mbarrier.arrive.expect_tx.shared.b64 _, [%0], %1;"      \
                     :: "r"(mb), "r"(CHUNKB) : "memory");                     \
        asm volatile(                                                         \
            "cp.async.bulk.shared::cluster.global.mbarrier::complete_tx::bytes" \
            " [%0], [%1], %2, [%3];"                                          \
            :: "r"(sm_stage), "l"(srcp), "r"(CHUNKB), "r"(mb) : "memory");    \
    } while (0)

__global__ __launch_bounds__(NT)
void hist_kernel(const float* __restrict__ x, float* __restrict__ out,
                 int nrows) {
    __shared__ __align__(1024) float4 buf[STAGES][CHUNKB / 16];
    __shared__ __align__(8) unsigned long long mbar_full[STAGES];
    __shared__ __align__(8) unsigned long long mbar_empty[STAGES];
    __shared__ unsigned swcnt[NT / 32][32];

    const int tid  = threadIdx.x;
    const int lane = tid & 31;
    const int warp = tid >> 5;
    const int bid  = blockIdx.x;
    const int grid = gridDim.x;

    // Rows owned by this CTA: bid, bid+grid, ... ; total chunks to stream.
    const int nown = (nrows - 1 - bid) / grid + 1;   // bid < nrows always here
    const int totc = nown * CPR;

    const char* base = reinterpret_cast<const char*>(x);

    // Global chunk id -> source byte address (rows strided by grid).
    auto src_of = [&](int c) -> const char* {
        int r = bid + (c >> 3) * grid;
        return base + (size_t)r * ROWB + (size_t)(c & (CPR - 1)) * CHUNKB;
    };

    if (tid == 0) {
        #pragma unroll
        for (int s = 0; s < STAGES; s++) {
            asm volatile("mbarrier.init.shared.b64 [%0], 1;"
                         :: "r"(smem_u32(&mbar_full[s])) : "memory");
            asm volatile("mbarrier.init.shared.b64 [%0], %1;"
                         :: "r"(smem_u32(&mbar_empty[s])), "r"(NT / 32) : "memory");
        }
        asm volatile("fence.proxy.async.shared::cta;" ::: "memory");
    }
    __syncthreads();

    // Prologue: fill the ring once (only cold start this CTA ever pays).
    if (tid == 0) {
        #pragma unroll
        for (int s = 0; s < STAGES; s++)
            if (s < totc)
                REFILL(smem_u32(&buf[s][0]), smem_u32(&mbar_full[s]), src_of(s));
    }

    // 8 bit-plane counters, weights 1..128 (cap 255; 128 elem/thread/row).
    unsigned ones = 0, twos = 0, fours = 0;
    unsigned a8 = 0, a16 = 0, a32 = 0, a64 = 0, a128 = 0;

    #pragma unroll 1
    for (int c = 0; c < totc; c++) {
        const int s = c & (STAGES - 1);
        const unsigned parity = (c / STAGES) & 1u;

        MB_WAIT(smem_u32(&mbar_full[s]), parity);

        const float4* b = &buf[s][0];
        float4 va = b[tid];
        float4 vb = b[tid + 128];
        float4 vc = b[tid + 256];
        float4 vd = b[tid + 384];

        unsigned h0 = bin_onehot(va.x), h1 = bin_onehot(va.y);
        unsigned h2 = bin_onehot(va.z), h3 = bin_onehot(va.w);
        unsigned h4 = bin_onehot(vb.x), h5 = bin_onehot(vb.y);
        unsigned h6 = bin_onehot(vb.z), h7 = bin_onehot(vb.w);
        unsigned g0 = bin_onehot(vc.x), g1 = bin_onehot(vc.y);
        unsigned g2 = bin_onehot(vc.z), g3 = bin_onehot(vc.w);
        unsigned g4 = bin_onehot(vd.x), g5 = bin_onehot(vd.y);
        unsigned g6 = bin_onehot(vd.z), g7 = bin_onehot(vd.w);

        // Warp's reads of stage s are in registers: signal empty (non-block).
        __syncwarp();
        if (lane == 0)
            asm volatile("mbarrier.arrive.shared.b64 _, [%0];"
                         :: "r"(smem_u32(&mbar_empty[s])) : "memory");

        unsigned c2a, c2b, c4a, c4b, e8a, e8b;
        csa(ones, c2a, ones, h0, h1);
        csa(ones, c2b, ones, h2, h3);
        csa(twos, c4a, twos, c2a, c2b);
        csa(ones, c2a, ones, h4, h5);
        csa(ones, c2b, ones, h6, h7);
        csa(twos, c4b, twos, c2a, c2b);
        csa(fours, e8a, fours, c4a, c4b);
        csa(ones, c2a, ones, g0, g1);
        csa(ones, c2b, ones, g2, g3);
        csa(twos, c4a, twos, c2a, c2b);
        csa(ones, c2a, ones, g4, g5);
        csa(ones, c2b, ones, g6, g7);
        csa(twos, c4b, twos, c2a, c2b);
        csa(fours, e8b, fours, c4a, c4b);
        unsigned c16;
        csa(a8, c16, a8, e8a, e8b);
        unsigned cc = a16 & c16; a16 ^= c16;
        unsigned dd = a32 & cc;  a32 ^= cc;
        cc = a64 & dd;  a64  ^= dd;
        a128 ^= cc;

        // Producer: refill stage s with chunk c+STAGES (rolls across rows).
        if (tid == 0 && c + STAGES < totc) {
            MB_WAIT(smem_u32(&mbar_empty[s]), parity);
            REFILL(smem_u32(&buf[s][0]), smem_u32(&mbar_full[s]),
                   src_of(c + STAGES));
        }

        // Row boundary: flush counters -> output, reset planes.
        if ((c & (CPR - 1)) == (CPR - 1)) {
            unsigned planes[8] = {ones, twos, fours, a8, a16, a32, a64, a128};
            unsigned cnt = 0;
            #pragma unroll
            for (int j = 0; j < 8; j++) {
                unsigned t = warp_bit_transpose(planes[j], lane);
                cnt += (unsigned)__popc(t) << j;
            }
            swcnt[warp][lane] = cnt;
            __syncthreads();
            if (warp == 0 && lane < NBINS) {
                unsigned total = swcnt[0][lane] + swcnt[1][lane]
                               + swcnt[2][lane] + swcnt[3][lane];
                int r = bid + (c >> 3) * grid;
                int pos = (lane == 0) ? 0 : (lane == NBINS - 1) ? 1 : (lane + 1);
                out[(size_t)r * NBINS + pos] = (float)total;
            }
            __syncthreads();   // swcnt safe for reuse next row
            ones = twos = fours = 0;
            a8 = a16 = a32 = a64 = a128 = 0;
        }
    }
}

extern "C" void kernel_launch(void* const* d_in, const int* in_sizes, int n_in,
                              void* d_out, int out_size) {
    const float* x = (const float*)d_in[0];
    float* out = (float*)d_out;
    int rows = in_sizes[0] / COLS;
    int grid = GRID < rows ? GRID : rows;
    hist_kernel<<<grid, NT>>>(x, out, rows);
}